// round 1
// baseline (speedup 1.0000x reference)
#include <cuda_runtime.h>
#include <math.h>
#include <stdint.h>

#define BB   4
#define LQV  1024
#define CCV  256
#define HHV  8
#define DHV  32
#define LLV  4
#define PPV  4
#define DFFV 1024
#define LSRCV 21760
#define MQ (BB*LQV)     // 4096
#define MS (BB*LSRCV)   // 87040

// ---------------- scratch (static device globals; no runtime allocation) ----
__device__ float g_qk  [MQ*CCV];
__device__ float g_q   [MQ*CCV];
__device__ float g_k   [MQ*CCV];
__device__ float g_v   [MQ*CCV];
__device__ float g_attn[MQ*CCV];
__device__ float g_res [MQ*CCV];
__device__ float g_tgta[MQ*CCV];
__device__ float g_value[(size_t)MS*CCV];
__device__ float g_q2  [MQ*CCV];
__device__ float g_off [MQ*CCV];
__device__ float g_aw  [MQ*HHV*LLV*PPV];
__device__ float g_samp[MQ*CCV];
__device__ float g_tgtb[MQ*CCV];
__device__ float g_hid [MQ*DFFV];

// ---------------- elementwise add -------------------------------------------
__global__ void add_kernel(const float* __restrict__ a, const float* __restrict__ b,
                           float* __restrict__ o, int n) {
    int i = blockIdx.x * blockDim.x + threadIdx.x;
    if (i < n) o[i] = a[i] + b[i];
}

// ---------------- generic GEMM: C = A(MxK) * W(NxK)^T + bias [+resid][relu] -
template<bool RELU, bool RESID>
__global__ __launch_bounds__(256) void gemm_kernel(
    const float* __restrict__ A, const float* __restrict__ W,
    const float* __restrict__ bias, const float* __restrict__ resid,
    float* __restrict__ C, int M, int N, int K)
{
    __shared__ float As[64][17];
    __shared__ float Bs[64][17];
    const int bm = blockIdx.y * 64;
    const int bn = blockIdx.x * 64;
    const int tid = threadIdx.x;
    const int tx = tid & 15;
    const int ty = tid >> 4;

    float acc[4][4] = {};

    const int lrow = tid >> 2;          // 0..63
    const int lcol = (tid & 3) * 4;     // 0,4,8,12

    for (int kt = 0; kt < K; kt += 16) {
        float4 av = *(const float4*)&A[(size_t)(bm + lrow) * K + kt + lcol];
        float4 wv = *(const float4*)&W[(size_t)(bn + lrow) * K + kt + lcol];
        As[lrow][lcol+0] = av.x; As[lrow][lcol+1] = av.y;
        As[lrow][lcol+2] = av.z; As[lrow][lcol+3] = av.w;
        Bs[lrow][lcol+0] = wv.x; Bs[lrow][lcol+1] = wv.y;
        Bs[lrow][lcol+2] = wv.z; Bs[lrow][lcol+3] = wv.w;
        __syncthreads();
        #pragma unroll
        for (int k = 0; k < 16; ++k) {
            float a0 = As[ty*4+0][k], a1 = As[ty*4+1][k];
            float a2 = As[ty*4+2][k], a3 = As[ty*4+3][k];
            float b0 = Bs[tx*4+0][k], b1 = Bs[tx*4+1][k];
            float b2 = Bs[tx*4+2][k], b3 = Bs[tx*4+3][k];
            acc[0][0] += a0*b0; acc[0][1] += a0*b1; acc[0][2] += a0*b2; acc[0][3] += a0*b3;
            acc[1][0] += a1*b0; acc[1][1] += a1*b1; acc[1][2] += a1*b2; acc[1][3] += a1*b3;
            acc[2][0] += a2*b0; acc[2][1] += a2*b1; acc[2][2] += a2*b2; acc[2][3] += a2*b3;
            acc[3][0] += a3*b0; acc[3][1] += a3*b1; acc[3][2] += a3*b2; acc[3][3] += a3*b3;
        }
        __syncthreads();
    }

    const int ncol = bn + tx*4;
    float4 bv = *(const float4*)&bias[ncol];
    #pragma unroll
    for (int i = 0; i < 4; ++i) {
        int m = bm + ty*4 + i;
        float4 out;
        out.x = acc[i][0] + bv.x; out.y = acc[i][1] + bv.y;
        out.z = acc[i][2] + bv.z; out.w = acc[i][3] + bv.w;
        if (RESID) {
            float4 rv = *(const float4*)&resid[(size_t)m * N + ncol];
            out.x += rv.x; out.y += rv.y; out.z += rv.z; out.w += rv.w;
        }
        if (RELU) {
            out.x = fmaxf(out.x, 0.f); out.y = fmaxf(out.y, 0.f);
            out.z = fmaxf(out.z, 0.f); out.w = fmaxf(out.w, 0.f);
        }
        *(float4*)&C[(size_t)m * N + ncol] = out;
    }
}

// ---------------- flash attention: warp-per-query, DH=32 --------------------
__global__ __launch_bounds__(256) void attn_kernel(
    const float* __restrict__ Q, const float* __restrict__ Kb,
    const float* __restrict__ Vb, float* __restrict__ O)
{
    __shared__ float Ks[64][33];
    __shared__ float Vs[64][33];
    __shared__ float Ps[8][64];
    const int bh = blockIdx.x;           // 0..31
    const int b = bh >> 3, h = bh & 7;
    const int w = threadIdx.x >> 5;
    const int lane = threadIdx.x & 31;
    const int q = blockIdx.y * 8 + w;

    const float scale = 0.17677669529663687f;  // 1/sqrt(32)
    float qv = Q[((size_t)(b*LQV + q))*CCV + h*DHV + lane] * scale;
    float qr[32];
    #pragma unroll
    for (int d = 0; d < 32; ++d) qr[d] = __shfl_sync(0xffffffffu, qv, d);

    float m = -1e30f, l = 0.f, acc = 0.f;

    for (int kt = 0; kt < LQV; kt += 64) {
        for (int i = threadIdx.x; i < 64*32; i += 256) {
            int r = i >> 5, c = i & 31;
            size_t gi = ((size_t)(b*LQV + kt + r))*CCV + h*DHV + c;
            Ks[r][c] = Kb[gi];
            Vs[r][c] = Vb[gi];
        }
        __syncthreads();

        float s0 = 0.f, s1 = 0.f;
        #pragma unroll
        for (int d = 0; d < 32; ++d) {
            s0 += qr[d] * Ks[lane][d];
            s1 += qr[d] * Ks[lane+32][d];
        }
        float tmax = fmaxf(s0, s1);
        #pragma unroll
        for (int o = 16; o > 0; o >>= 1)
            tmax = fmaxf(tmax, __shfl_xor_sync(0xffffffffu, tmax, o));
        float mn = fmaxf(m, tmax);
        float p0 = __expf(s0 - mn), p1 = __expf(s1 - mn);
        float sc = __expf(m - mn);
        float ps = p0 + p1;
        #pragma unroll
        for (int o = 16; o > 0; o >>= 1)
            ps += __shfl_xor_sync(0xffffffffu, ps, o);
        l = l * sc + ps;
        m = mn;
        Ps[w][lane] = p0; Ps[w][lane+32] = p1;
        __syncwarp();
        float a = 0.f;
        #pragma unroll
        for (int j = 0; j < 64; ++j) a += Ps[w][j] * Vs[j][lane];
        acc = acc * sc + a;
        __syncthreads();
    }
    O[((size_t)(b*LQV + q))*CCV + h*DHV + lane] = acc / l;
}

// ---------------- LayerNorm: block per row (C=256) --------------------------
__global__ __launch_bounds__(256) void ln_kernel(
    const float* __restrict__ x, const float* __restrict__ g,
    const float* __restrict__ b, float* __restrict__ y)
{
    const int row = blockIdx.x;
    const int t = threadIdx.x;
    float v = x[(size_t)row * 256 + t];
    float s = v, sq = v * v;
    #pragma unroll
    for (int o = 16; o > 0; o >>= 1) {
        s  += __shfl_xor_sync(0xffffffffu, s,  o);
        sq += __shfl_xor_sync(0xffffffffu, sq, o);
    }
    __shared__ float sh1[8], sh2[8];
    int wid = t >> 5, lane = t & 31;
    if (lane == 0) { sh1[wid] = s; sh2[wid] = sq; }
    __syncthreads();
    float S = 0.f, SQ = 0.f;
    #pragma unroll
    for (int i = 0; i < 8; ++i) { S += sh1[i]; SQ += sh2[i]; }
    float mean = S * (1.f/256.f);
    float var  = SQ * (1.f/256.f) - mean * mean;
    y[(size_t)row * 256 + t] = (v - mean) * rsqrtf(var + 1e-5f) * g[t] + b[t];
}

// ---------------- attention-weight softmax over L*P=16 ----------------------
__global__ void awsm_kernel(const float* __restrict__ in, float* __restrict__ out) {
    int i = blockIdx.x * blockDim.x + threadIdx.x;   // (b*LQ+q)*H + h
    if (i >= MQ * HHV) return;
    int bq = i >> 3, h = i & 7;
    const float* p = in + (size_t)bq * 128 + h * 16;
    float vals[16], mx = -1e30f;
    #pragma unroll
    for (int k = 0; k < 16; ++k) { vals[k] = p[k]; mx = fmaxf(mx, vals[k]); }
    float sum = 0.f;
    #pragma unroll
    for (int k = 0; k < 16; ++k) { vals[k] = __expf(vals[k] - mx); sum += vals[k]; }
    float inv = 1.f / sum;
    float* o = out + (size_t)bq * 128 + h * 16;
    #pragma unroll
    for (int k = 0; k < 16; ++k) o[k] = vals[k] * inv;
}

// ---------------- deformable sampling: warp per (b,q,h) ---------------------
__global__ __launch_bounds__(256) void deform_kernel(
    const float* __restrict__ val, const float* __restrict__ ref,
    const float* __restrict__ offs, const float* __restrict__ aw,
    float* __restrict__ out)
{
    const int gw = (blockIdx.x * blockDim.x + threadIdx.x) >> 5;  // warp id
    const int lane = threadIdx.x & 31;
    if (gw >= MQ * HHV) return;
    const int bq = gw >> 3, h = gw & 7;
    const int b = bq >> 10;   // LQ=1024

    const int starts[4] = {0, 16384, 20480, 21504};
    const int WL[4]     = {128, 64, 32, 16};

    const float* offp = offs + (size_t)bq * 256 + h * 32;
    const float* awp  = aw   + (size_t)bq * 128 + h * 16;
    const float* refp = ref  + (size_t)bq * 8;

    float acc = 0.f;
    #pragma unroll
    for (int l = 0; l < 4; ++l) {
        const int wl = WL[l];
        const float fwl = (float)wl;
        const float rx = refp[l*2+0], ry = refp[l*2+1];
        const int base_l = b * LSRCV + starts[l];
        #pragma unroll
        for (int p = 0; p < 4; ++p) {
            float ox = offp[l*8 + p*2 + 0];
            float oy = offp[l*8 + p*2 + 1];
            float a  = awp[l*4 + p];
            float lx = rx + ox / fwl;
            float ly = ry + oy / fwl;
            float x = lx * fwl - 0.5f;
            float y = ly * fwl - 0.5f;
            float x0f = floorf(x), y0f = floorf(y);
            int x0 = (int)x0f, y0 = (int)y0f;
            float wx1 = x - x0f, wx0 = 1.f - wx1;
            float wy1 = y - y0f, wy0 = 1.f - wy1;
            #pragma unroll
            for (int dy = 0; dy < 2; ++dy) {
                #pragma unroll
                for (int dx = 0; dx < 2; ++dx) {
                    int xi = x0 + dx, yi = y0 + dy;
                    if (xi >= 0 && xi < wl && yi >= 0 && yi < wl) {
                        float wgt = (dx ? wx1 : wx0) * (dy ? wy1 : wy0);
                        float vv = val[((size_t)(base_l + yi*wl + xi))*CCV + h*32 + lane];
                        acc += a * wgt * vv;
                    }
                }
            }
        }
    }
    out[(size_t)bq * 256 + h * 32 + lane] = acc;
}

// ---------------- orchestration ---------------------------------------------
extern "C" void kernel_launch(void* const* d_in, const int* in_sizes, int n_in,
                              void* d_out, int out_size)
{
    const float* tgt   = (const float*)d_in[0];
    const float* qpos  = (const float*)d_in[1];
    const float* refp  = (const float*)d_in[2];
    const float* src   = (const float*)d_in[3];
    const float* in_w  = (const float*)d_in[4];
    const float* in_b  = (const float*)d_in[5];
    const float* sa_w  = (const float*)d_in[6];
    const float* sa_b  = (const float*)d_in[7];
    const float* off_w = (const float*)d_in[8];
    const float* off_b = (const float*)d_in[9];
    const float* aw_w  = (const float*)d_in[10];
    const float* aw_b  = (const float*)d_in[11];
    const float* val_w = (const float*)d_in[12];
    const float* val_b = (const float*)d_in[13];
    const float* co_w  = (const float*)d_in[14];
    const float* co_b  = (const float*)d_in[15];
    const float* ln1_g = (const float*)d_in[16];
    const float* ln1_b = (const float*)d_in[17];
    const float* ln2_g = (const float*)d_in[18];
    const float* ln2_b = (const float*)d_in[19];
    const float* ln3_g = (const float*)d_in[20];
    const float* ln3_b = (const float*)d_in[21];
    const float* f1_w  = (const float*)d_in[22];
    const float* f1_b  = (const float*)d_in[23];
    const float* f2_w  = (const float*)d_in[24];
    const float* f2_b  = (const float*)d_in[25];
    float* out = (float*)d_out;

    float *p_qk, *p_q, *p_k, *p_v, *p_attn, *p_res, *p_tgta, *p_value;
    float *p_q2, *p_off, *p_aw, *p_samp, *p_tgtb, *p_hid;
    cudaGetSymbolAddress((void**)&p_qk,   g_qk);
    cudaGetSymbolAddress((void**)&p_q,    g_q);
    cudaGetSymbolAddress((void**)&p_k,    g_k);
    cudaGetSymbolAddress((void**)&p_v,    g_v);
    cudaGetSymbolAddress((void**)&p_attn, g_attn);
    cudaGetSymbolAddress((void**)&p_res,  g_res);
    cudaGetSymbolAddress((void**)&p_tgta, g_tgta);
    cudaGetSymbolAddress((void**)&p_value,g_value);
    cudaGetSymbolAddress((void**)&p_q2,   g_q2);
    cudaGetSymbolAddress((void**)&p_off,  g_off);
    cudaGetSymbolAddress((void**)&p_aw,   g_aw);
    cudaGetSymbolAddress((void**)&p_samp, g_samp);
    cudaGetSymbolAddress((void**)&p_tgtb, g_tgtb);
    cudaGetSymbolAddress((void**)&p_hid,  g_hid);

    const int NQ = MQ * CCV;  // 1048576

    // ---- self-attention ----
    add_kernel<<<NQ/256, 256>>>(tgt, qpos, p_qk, NQ);
    gemm_kernel<false,false><<<dim3(4,64), 256>>>(p_qk, in_w,          in_b,       nullptr, p_q, MQ, 256, 256);
    gemm_kernel<false,false><<<dim3(4,64), 256>>>(p_qk, in_w + 256*256, in_b + 256, nullptr, p_k, MQ, 256, 256);
    gemm_kernel<false,false><<<dim3(4,64), 256>>>(tgt,  in_w + 512*256, in_b + 512, nullptr, p_v, MQ, 256, 256);
    attn_kernel<<<dim3(32,128), 256>>>(p_q, p_k, p_v, p_attn);
    gemm_kernel<false,true ><<<dim3(4,64), 256>>>(p_attn, sa_w, sa_b, tgt, p_res, MQ, 256, 256);
    ln_kernel<<<MQ, 256>>>(p_res, ln2_g, ln2_b, p_tgta);

    // ---- deformable cross-attention ----
    gemm_kernel<false,false><<<dim3(4,1360), 256>>>(src, val_w, val_b, nullptr, p_value, MS, 256, 256);
    add_kernel<<<NQ/256, 256>>>(p_tgta, qpos, p_q2, NQ);
    gemm_kernel<false,false><<<dim3(4,64), 256>>>(p_q2, off_w, off_b, nullptr, p_off, MQ, 256, 256);
    gemm_kernel<false,false><<<dim3(2,64), 256>>>(p_q2, aw_w,  aw_b,  nullptr, p_res, MQ, 128, 256);
    awsm_kernel<<<128, 256>>>(p_res, p_aw);
    deform_kernel<<<4096, 256>>>(p_value, refp, p_off, p_aw, p_samp);
    gemm_kernel<false,true ><<<dim3(4,64), 256>>>(p_samp, co_w, co_b, p_tgta, p_res, MQ, 256, 256);
    ln_kernel<<<MQ, 256>>>(p_res, ln1_g, ln1_b, p_tgtb);

    // ---- FFN ----
    gemm_kernel<true ,false><<<dim3(16,64), 256>>>(p_tgtb, f1_w, f1_b, nullptr, p_hid, MQ, 1024, 256);
    gemm_kernel<false,true ><<<dim3(4,64), 256>>>(p_hid, f2_w, f2_b, p_tgtb, p_res, MQ, 256, 1024);
    ln_kernel<<<MQ, 256>>>(p_res, ln3_g, ln3_b, out);
}